// round 14
// baseline (speedup 1.0000x reference)
#include <cuda_runtime.h>
#include <math_constants.h>

#define B_    64
#define J_    8
#define D_    256
#define NEG_  2048             // K*M
#define NPB_  256              // negatives per block
#define SPLIT_ (NEG_/NPB_)     // 8 chunks per batch
#define NEGBLK_ (B_*SPLIT_)    // 512 negative blocks
#define POSBLK_ B_             // 64 dedicated pos blocks
#define NBLOCKS_ (NEGBLK_+POSBLK_)  // 576
#define THREADS_ 128
#define WPB_  4                // warps per block
#define MAXE_ 6                // covers n<=24 per block (tail loop for the rest)
#define NARRIVE_ (NEGBLK_*WPB_ + POSBLK_)   // 2112 warp-level arrivals
#define INV_TEMP 10.0f

// Scratch (device globals; counter reset by finalizer for graph replay)
__device__ float        g_part4[NEGBLK_ * WPB_];  // per-WARP exp-sums
__device__ float        g_pos[B_];                // per-batch pos_sim
__device__ unsigned int g_count;                  // warp arrival counter

// Arrival with release semantics: orders prior global stores without a
// separate MEMBAR on the critical path.
__device__ __forceinline__ unsigned int arrive_release(unsigned int* ctr) {
    unsigned int old;
    asm volatile("atom.release.gpu.global.add.u32 %0, [%1], 1;"
                 : "=r"(old) : "l"(ctr) : "memory");
    return old;
}

// ---------------------------------------------------------------------------
// One kernel, 576 blocks x 128 threads. R13 base with a warp-autonomous tail:
// each warp stores its own g_part4 slot and arrives independently (release
// atomic); NO end-of-block barrier or serial combine. The last arriving WARP
// finalizes (2 batches per lane, 8 float4 partial reads each).
// ---------------------------------------------------------------------------
__global__ void __launch_bounds__(THREADS_) ntxent_kernel(
    const float* __restrict__ childrens,   // (B, J, D)
    const float* __restrict__ pos,         // (B, J, D)
    const float* __restrict__ negs,        // (B, NEG, D)
    const int*   __restrict__ labels,      // (B, J)
    const int*   __restrict__ neg_labels,  // (B, NEG)
    float*       __restrict__ out)
{
    const int bx   = blockIdx.x;
    const int tid  = threadIdx.x;
    const int warp = tid >> 5;
    const int lane = tid & 31;

    bool arriving = false;   // does this warp arrive on the counter?

    if (bx >= NEGBLK_) {
        // ================= dedicated pos block =================
        if (warp != 0) return;          // idle warps exit, no arrival
        const int b = bx - NEGBLK_;
        const float* cp = childrens + ((size_t)b * J_ + (J_ - 1)) * D_;
        const float* pp = pos       + ((size_t)b * J_ + (J_ - 1)) * D_;
        float4 ca = ((const float4*)cp)[lane];
        float4 cb = ((const float4*)cp)[lane + 32];
        float4 pa = ((const float4*)pp)[lane];
        float4 pb = ((const float4*)pp)[lane + 32];
        float dot = ca.x*pa.x + ca.y*pa.y + ca.z*pa.z + ca.w*pa.w
                  + cb.x*pb.x + cb.y*pb.y + cb.z*pb.z + cb.w*pb.w;
        float cs  = ca.x*ca.x + ca.y*ca.y + ca.z*ca.z + ca.w*ca.w
                  + cb.x*cb.x + cb.y*cb.y + cb.z*cb.z + cb.w*cb.w;
        float ps  = pa.x*pa.x + pa.y*pa.y + pa.z*pa.z + pa.w*pa.w
                  + pb.x*pb.x + pb.y*pb.y + pb.z*pb.z + pb.w*pb.w;
        #pragma unroll
        for (int o = 16; o; o >>= 1) {
            dot += __shfl_xor_sync(0xffffffffu, dot, o);
            cs  += __shfl_xor_sync(0xffffffffu, cs,  o);
            ps  += __shfl_xor_sync(0xffffffffu, ps,  o);
        }
        if (lane == 0)
            g_pos[b] = dot * rsqrtf(cs) * rsqrtf(ps) * INV_TEMP;
        arriving = true;
    } else {
        // ================= negative block =================
        const int b     = bx >> 3;              // / SPLIT_
        const int chunk = bx & (SPLIT_ - 1);
        const int nbase = chunk * NPB_;

        __shared__ short s_list[WPB_ * 64];     // per-warp regions, 64 slots each
        __shared__ int   s_cnt[WPB_];

        // ---- issue all independent loads up front ----
        const int label = __ldg(labels + b * J_ + (J_ - 1));
        const int2 ml2  = __ldg((const int2*)(neg_labels + (size_t)b * NEG_ + nbase) + tid);

        const float* cp = childrens + ((size_t)b * J_ + (J_ - 1)) * D_;
        const float4 ca = ((const float4*)cp)[lane];
        const float4 cb = ((const float4*)cp)[lane + 32];

        // ---- child inv-norm (overlaps label trip) ----
        float cs = ca.x*ca.x + ca.y*ca.y + ca.z*ca.z + ca.w*ca.w
                 + cb.x*cb.x + cb.y*cb.y + cb.z*cb.z + cb.w*cb.w;
        #pragma unroll
        for (int o = 16; o; o >>= 1) cs += __shfl_xor_sync(0xffffffffu, cs, o);
        const float invcn = rsqrtf(cs);

        // ---- ballot compaction into per-warp region: ONE sync publishes all ----
        const bool h0 = (ml2.x == label);
        const bool h1 = (ml2.y == label);
        const unsigned int b0 = __ballot_sync(0xffffffffu, h0);
        const unsigned int b1 = __ballot_sync(0xffffffffu, h1);
        const unsigned int lt = (1u << lane) - 1u;
        const int cnt_lt = __popc(b0 & lt) + __popc(b1 & lt);
        if (h0) s_list[warp * 64 + cnt_lt]            = (short)(tid * 2);
        if (h1) s_list[warp * 64 + cnt_lt + (h0?1:0)] = (short)(tid * 2 + 1);
        if (lane == 0) s_cnt[warp] = __popc(b0) + __popc(b1);
        __syncthreads();

        const int c0 = s_cnt[0], c1 = s_cnt[1], c2 = s_cnt[2], c3 = s_cnt[3];
        const int n  = c0 + c1 + c2 + c3;
        const int e01 = c0 + c1, e012 = e01 + c2;

        const float* negbase = negs + ((size_t)b * NEG_ + nbase) * D_;

        // Map global entry index e -> per-warp-region slot (3 compares, ALU only).
        #define SLOT(e) ((e) < c0 ? (e) : (e) < e01 ? 64 + (e) - c0 \
                        : (e) < e012 ? 128 + (e) - e01 : 192 + (e) - e012)

        // ---- register-batched gather: all loads issued back-to-back ----
        float4 Aa[MAXE_], Ac[MAXE_];
        #pragma unroll
        for (int k = 0; k < MAXE_; k++) {
            const int e = warp + k * WPB_;
            if (e < n) {
                const float4* p = (const float4*)(negbase + (size_t)s_list[SLOT(e)] * D_);
                Aa[k] = p[lane];
                Ac[k] = p[lane + 32];
            }
        }

        float dot[MAXE_], ssq[MAXE_];
        #pragma unroll
        for (int k = 0; k < MAXE_; k++) {
            const int e = warp + k * WPB_;
            if (e < n) {
                dot[k] = Aa[k].x*ca.x + Aa[k].y*ca.y + Aa[k].z*ca.z + Aa[k].w*ca.w
                       + Ac[k].x*cb.x + Ac[k].y*cb.y + Ac[k].z*cb.z + Ac[k].w*cb.w;
                ssq[k] = Aa[k].x*Aa[k].x + Aa[k].y*Aa[k].y + Aa[k].z*Aa[k].z + Aa[k].w*Aa[k].w
                       + Ac[k].x*Ac[k].x + Ac[k].y*Ac[k].y + Ac[k].z*Ac[k].z + Ac[k].w*Ac[k].w;
            } else {
                dot[k] = 0.0f; ssq[k] = 1.0f;
            }
        }

        // Interleaved butterflies: 2*MAXE_ independent SHFL chains.
        #pragma unroll
        for (int o = 16; o; o >>= 1) {
            #pragma unroll
            for (int k = 0; k < MAXE_; k++) {
                dot[k] += __shfl_xor_sync(0xffffffffu, dot[k], o);
                ssq[k] += __shfl_xor_sync(0xffffffffu, ssq[k], o);
            }
        }

        // ---- bounded sims -> plain exp-sum (rsqrtf, no division) ----
        float acc = 0.0f;
        #pragma unroll
        for (int k = 0; k < MAXE_; k++) {
            const int e = warp + k * WPB_;
            if (e < n)
                acc += __expf(dot[k] * invcn * rsqrtf(ssq[k]) * INV_TEMP);
        }

        // ---- rare tail (n > 24) ----
        for (int e = warp + MAXE_ * WPB_; e < n; e += WPB_) {
            const float4* p = (const float4*)(negbase + (size_t)s_list[SLOT(e)] * D_);
            float4 a = p[lane];
            float4 c = p[lane + 32];
            float d2 = a.x*ca.x + a.y*ca.y + a.z*ca.z + a.w*ca.w
                     + c.x*cb.x + c.y*cb.y + c.z*cb.z + c.w*cb.w;
            float q2 = a.x*a.x + a.y*a.y + a.z*a.z + a.w*a.w
                     + c.x*c.x + c.y*c.y + c.z*c.z + c.w*c.w;
            #pragma unroll
            for (int o = 16; o; o >>= 1) {
                d2 += __shfl_xor_sync(0xffffffffu, d2, o);
                q2 += __shfl_xor_sync(0xffffffffu, q2, o);
            }
            acc += __expf(d2 * invcn * rsqrtf(q2) * INV_TEMP);
        }
        #undef SLOT

        // ---- warp-autonomous finish: direct store, NO end-of-block barrier ----
        if (lane == 0)
            g_part4[bx * WPB_ + warp] = acc;
        arriving = true;
    }

    // ---- per-WARP arrival: release-atomic; last warp finalizes alone ----
    int fin = 0;
    if (arriving && lane == 0) {
        unsigned int old = arrive_release(&g_count);
        fin = (old == NARRIVE_ - 1) ? 1 : 0;
    }
    fin = __shfl_sync(0xffffffffu, fin, 0);
    if (!fin) return;

    __threadfence();   // acquire all warps' g_part4 / g_pos

    // ---- finalize in ONE warp: 2 batches per lane ----
    float total = 0.0f;
    #pragma unroll
    for (int r = 0; r < 2; r++) {
        const int bb = lane + r * 32;
        // batch bb's 32 warp partials: g_part4[bb*32 .. bb*32+31]
        const float4* pr = (const float4*)(g_part4 + bb * (SPLIT_ * WPB_));
        float S = 0.0f;
        #pragma unroll
        for (int q = 0; q < 8; q++) {
            float4 p = pr[q];
            S += (p.x + p.y) + (p.z + p.w);
        }
        const float psim = g_pos[bb];
        total += __logf(S + __expf(psim)) - psim;
    }
    #pragma unroll
    for (int o = 16; o; o >>= 1) total += __shfl_xor_sync(0xffffffffu, total, o);
    if (lane == 0) {
        out[0] = total / (2.0f * (float)B_);
        g_count = 0;   // reset for next graph replay
    }
}

extern "C" void kernel_launch(void* const* d_in, const int* in_sizes, int n_in,
                              void* d_out, int out_size) {
    const float* childrens  = (const float*)d_in[0]; // (B, J, D)
    const float* child_pos  = (const float*)d_in[1]; // (B, J, D)
    const float* child_negs = (const float*)d_in[2]; // (B, K, M, D)
    const int*   gt_labels  = (const int*)d_in[3];   // (B, J)
    const int*   gt_negs    = (const int*)d_in[4];   // (B, K, M)
    float* out = (float*)d_out;

    ntxent_kernel<<<NBLOCKS_, THREADS_>>>(childrens, child_pos, child_negs,
                                          gt_labels, gt_negs, out);
}

// round 15
// speedup vs baseline: 1.2362x; 1.2362x over previous
#include <cuda_runtime.h>
#include <math_constants.h>

#define B_    64
#define J_    8
#define D_    256
#define NEG_  2048             // K*M
#define NPB_  256              // negatives per block
#define SPLIT_ (NEG_/NPB_)     // 8 chunks per batch
#define NEGBLK_ (B_*SPLIT_)    // 512 negative blocks
#define POSBLK_ B_             // 64 dedicated pos blocks
#define NBLOCKS_ (NEGBLK_+POSBLK_)  // 576
#define THREADS_ 128
#define WPB_  4                // warps per block
#define MAXE_ 6                // covers n<=24 per block (tail loop for the rest)
#define INV_TEMP 10.0f
#define INV_2B  (1.0f / 128.0f)   // 1/(2*B_)

// Scratch (device globals; counter reset by finalizer for graph replay)
__device__ float        g_part[NEGBLK_];  // per-neg-block sum of exp(sim)
__device__ float        g_pos[B_];        // per-batch pos_sim
__device__ unsigned int g_count;          // single arrival counter (576)

// Arrival with release semantics: orders prior global stores without a
// separate MEMBAR on the critical path.
__device__ __forceinline__ unsigned int arrive_release(unsigned int* ctr) {
    unsigned int old;
    asm volatile("atom.release.gpu.global.add.u32 %0, [%1], 1;"
                 : "=r"(old) : "l"(ctr) : "memory");
    return old;
}

// ---------------------------------------------------------------------------
// R13 champion (8.93us): 576 blocks x 128 threads.
//  - single-sync ballot compaction into per-warp s_list regions
//  - register-batched gather (MAXE_=6), interleaved SHFL butterflies
//  - plain exp-sum (sims bounded by +-10), rsqrtf, __logf finalize
//  - ONE block-level release-atomic arrival (576 arrivals total)
// ---------------------------------------------------------------------------
__global__ void __launch_bounds__(THREADS_) ntxent_kernel(
    const float* __restrict__ childrens,   // (B, J, D)
    const float* __restrict__ pos,         // (B, J, D)
    const float* __restrict__ negs,        // (B, NEG, D)
    const int*   __restrict__ labels,      // (B, J)
    const int*   __restrict__ neg_labels,  // (B, NEG)
    float*       __restrict__ out)
{
    const int bx   = blockIdx.x;
    const int tid  = threadIdx.x;
    const int warp = tid >> 5;
    const int lane = tid & 31;

    __shared__ int s_last;

    if (bx >= NEGBLK_) {
        // ================= dedicated pos block =================
        const int b = bx - NEGBLK_;
        if (warp == 0) {
            const float* cp = childrens + ((size_t)b * J_ + (J_ - 1)) * D_;
            const float* pp = pos       + ((size_t)b * J_ + (J_ - 1)) * D_;
            float4 ca = ((const float4*)cp)[lane];
            float4 cb = ((const float4*)cp)[lane + 32];
            float4 pa = ((const float4*)pp)[lane];
            float4 pb = ((const float4*)pp)[lane + 32];
            float dot = ca.x*pa.x + ca.y*pa.y + ca.z*pa.z + ca.w*pa.w
                      + cb.x*pb.x + cb.y*pb.y + cb.z*pb.z + cb.w*pb.w;
            float cs  = ca.x*ca.x + ca.y*ca.y + ca.z*ca.z + ca.w*ca.w
                      + cb.x*cb.x + cb.y*cb.y + cb.z*cb.z + cb.w*cb.w;
            float ps  = pa.x*pa.x + pa.y*pa.y + pa.z*pa.z + pa.w*pa.w
                      + pb.x*pb.x + pb.y*pb.y + pb.z*pb.z + pb.w*pb.w;
            #pragma unroll
            for (int o = 16; o; o >>= 1) {
                dot += __shfl_xor_sync(0xffffffffu, dot, o);
                cs  += __shfl_xor_sync(0xffffffffu, cs,  o);
                ps  += __shfl_xor_sync(0xffffffffu, ps,  o);
            }
            if (lane == 0)
                g_pos[b] = dot * rsqrtf(cs) * rsqrtf(ps) * INV_TEMP;
        }
    } else {
        // ================= negative block =================
        const int b     = bx >> 3;              // / SPLIT_
        const int chunk = bx & (SPLIT_ - 1);
        const int nbase = chunk * NPB_;

        __shared__ short s_list[WPB_ * 64];     // per-warp regions, 64 slots each
        __shared__ int   s_cnt[WPB_];

        // ---- issue all independent loads up front ----
        const int label = __ldg(labels + b * J_ + (J_ - 1));
        const int2 ml2  = __ldg((const int2*)(neg_labels + (size_t)b * NEG_ + nbase) + tid);

        const float* cp = childrens + ((size_t)b * J_ + (J_ - 1)) * D_;
        const float4 ca = ((const float4*)cp)[lane];
        const float4 cb = ((const float4*)cp)[lane + 32];

        // ---- child inv-norm (overlaps label trip) ----
        float cs = ca.x*ca.x + ca.y*ca.y + ca.z*ca.z + ca.w*ca.w
                 + cb.x*cb.x + cb.y*cb.y + cb.z*cb.z + cb.w*cb.w;
        #pragma unroll
        for (int o = 16; o; o >>= 1) cs += __shfl_xor_sync(0xffffffffu, cs, o);
        const float invcn = rsqrtf(cs);

        // ---- ballot compaction into per-warp region: ONE sync publishes all ----
        const bool h0 = (ml2.x == label);
        const bool h1 = (ml2.y == label);
        const unsigned int b0 = __ballot_sync(0xffffffffu, h0);
        const unsigned int b1 = __ballot_sync(0xffffffffu, h1);
        const unsigned int lt = (1u << lane) - 1u;
        const int cnt_lt = __popc(b0 & lt) + __popc(b1 & lt);
        if (h0) s_list[warp * 64 + cnt_lt]            = (short)(tid * 2);
        if (h1) s_list[warp * 64 + cnt_lt + (h0?1:0)] = (short)(tid * 2 + 1);
        if (lane == 0) s_cnt[warp] = __popc(b0) + __popc(b1);
        __syncthreads();

        const int c0 = s_cnt[0], c1 = s_cnt[1], c2 = s_cnt[2], c3 = s_cnt[3];
        const int n  = c0 + c1 + c2 + c3;
        const int e01 = c0 + c1, e012 = e01 + c2;

        const float* negbase = negs + ((size_t)b * NEG_ + nbase) * D_;

        // Map global entry index e -> per-warp-region slot (3 compares, ALU only).
        #define SLOT(e) ((e) < c0 ? (e) : (e) < e01 ? 64 + (e) - c0 \
                        : (e) < e012 ? 128 + (e) - e01 : 192 + (e) - e012)

        // ---- register-batched gather: all loads issued back-to-back ----
        float4 Aa[MAXE_], Ac[MAXE_];
        #pragma unroll
        for (int k = 0; k < MAXE_; k++) {
            const int e = warp + k * WPB_;
            if (e < n) {
                const float4* p = (const float4*)(negbase + (size_t)s_list[SLOT(e)] * D_);
                Aa[k] = p[lane];
                Ac[k] = p[lane + 32];
            }
        }

        float dot[MAXE_], ssq[MAXE_];
        #pragma unroll
        for (int k = 0; k < MAXE_; k++) {
            const int e = warp + k * WPB_;
            if (e < n) {
                dot[k] = Aa[k].x*ca.x + Aa[k].y*ca.y + Aa[k].z*ca.z + Aa[k].w*ca.w
                       + Ac[k].x*cb.x + Ac[k].y*cb.y + Ac[k].z*cb.z + Ac[k].w*cb.w;
                ssq[k] = Aa[k].x*Aa[k].x + Aa[k].y*Aa[k].y + Aa[k].z*Aa[k].z + Aa[k].w*Aa[k].w
                       + Ac[k].x*Ac[k].x + Ac[k].y*Ac[k].y + Ac[k].z*Ac[k].z + Ac[k].w*Ac[k].w;
            } else {
                dot[k] = 0.0f; ssq[k] = 1.0f;
            }
        }

        // Interleaved butterflies: 2*MAXE_ independent SHFL chains.
        #pragma unroll
        for (int o = 16; o; o >>= 1) {
            #pragma unroll
            for (int k = 0; k < MAXE_; k++) {
                dot[k] += __shfl_xor_sync(0xffffffffu, dot[k], o);
                ssq[k] += __shfl_xor_sync(0xffffffffu, ssq[k], o);
            }
        }

        // ---- bounded sims -> plain exp-sum (rsqrtf, no division) ----
        float acc = 0.0f;
        #pragma unroll
        for (int k = 0; k < MAXE_; k++) {
            const int e = warp + k * WPB_;
            if (e < n)
                acc += __expf(dot[k] * invcn * rsqrtf(ssq[k]) * INV_TEMP);
        }

        // ---- rare tail (n > 24) ----
        for (int e = warp + MAXE_ * WPB_; e < n; e += WPB_) {
            const float4* p = (const float4*)(negbase + (size_t)s_list[SLOT(e)] * D_);
            float4 a = p[lane];
            float4 c = p[lane + 32];
            float d2 = a.x*ca.x + a.y*ca.y + a.z*ca.z + a.w*ca.w
                     + c.x*cb.x + c.y*cb.y + c.z*cb.z + c.w*cb.w;
            float q2 = a.x*a.x + a.y*a.y + a.z*a.z + a.w*a.w
                     + c.x*c.x + c.y*c.y + c.z*c.z + c.w*c.w;
            #pragma unroll
            for (int o = 16; o; o >>= 1) {
                d2 += __shfl_xor_sync(0xffffffffu, d2, o);
                q2 += __shfl_xor_sync(0xffffffffu, q2, o);
            }
            acc += __expf(d2 * invcn * rsqrtf(q2) * INV_TEMP);
        }
        #undef SLOT

        // ---- combine 4 warp sums via smem ----
        __shared__ float s_w[WPB_];
        if (lane == 0) s_w[warp] = acc;
        __syncthreads();

        if (tid == 0)
            g_part[bx] = s_w[0] + s_w[1] + s_w[2] + s_w[3];
    }

    // ---- arrival: release-atomic, last block finalizes ----
    if (tid == 0) {
        unsigned int old = arrive_release(&g_count);
        s_last = (old == NBLOCKS_ - 1) ? 1 : 0;
    }
    __syncthreads();
    if (!s_last) return;

    __threadfence();   // acquire all blocks' g_part / g_pos

    // ---- finalize: 64 threads, one batch each; fast log; tree-sum ----
    __shared__ float s_loss[B_];
    if (tid < B_) {
        const int bb = tid;
        const float4* pr = (const float4*)(g_part + bb * SPLIT_);
        float4 p0 = pr[0], p1 = pr[1];
        float S = ((p0.x + p0.y) + (p0.z + p0.w)) + ((p1.x + p1.y) + (p1.z + p1.w));
        const float psim = g_pos[bb];
        s_loss[bb] = __logf(S + __expf(psim)) - psim;
    }
    __syncthreads();

    if (tid < 32) {
        float v = s_loss[tid] + s_loss[tid + 32];
        #pragma unroll
        for (int o = 16; o; o >>= 1) v += __shfl_xor_sync(0xffffffffu, v, o);
        if (tid == 0) {
            out[0] = v * INV_2B;
            g_count = 0;   // reset for next graph replay
        }
    }
}

extern "C" void kernel_launch(void* const* d_in, const int* in_sizes, int n_in,
                              void* d_out, int out_size) {
    const float* childrens  = (const float*)d_in[0]; // (B, J, D)
    const float* child_pos  = (const float*)d_in[1]; // (B, J, D)
    const float* child_negs = (const float*)d_in[2]; // (B, K, M, D)
    const int*   gt_labels  = (const int*)d_in[3];   // (B, J)
    const int*   gt_negs    = (const int*)d_in[4];   // (B, K, M)
    float* out = (float*)d_out;

    ntxent_kernel<<<NBLOCKS_, THREADS_>>>(childrens, child_pos, child_negs,
                                          gt_labels, gt_negs, out);
}